// round 14
// baseline (speedup 1.0000x reference)
#include <cuda_runtime.h>
#include <cuda_fp16.h>
#include <mma.h>
#include <math.h>
#include <stdint.h>

using namespace nvcuda;

// ---------------- problem constants ----------------
#define BB 8
#define T1C 32
#define T2C 32
#define JC 33
#define KSEG 9
#define NN 8448
#define EC 256
#define HC 512
#define UC 1024
#define GHC 2048
#define VC 8000
#define START_ID 8001
#define GIN_ROWS 2376
#define GIN_ROWS_PAD 2432

typedef __half hf;
typedef __half2 hf2;

// ---------------- device scratch ----------------
__device__ hf    d_X1[NN * 1024];             // [h0 | h1] per row (fp16)
__device__ float d_c0[NN * HC];
__device__ float d_c1[NN * HC];
__device__ hf    d_fco[2 * NN * EC];          // double-buffered across steps
__device__ float d_gin[GIN_ROWS_PAD * GHC];
__device__ float d_gctx[256 * GHC];
__device__ hf    d_ctxb[256 * HC];
__device__ float d_hinit[2 * BB * HC];
__device__ float d_cinit[2 * BB * HC];
__device__ float d_cum[NN];
__device__ float d_b0p[GHC];
__device__ float d_b1p[GHC];
__device__ int   d_ginoff[GIN_ROWS_PAD];
__device__ int   d_ctxoff[256];
__device__ int   d_tgttok[GIN_ROWS];
__device__ hf d_Whh0b[GHC * HC];
__device__ hf d_W1catb[GHC * 1024];
__device__ hf d_Wfcb[EC * HC];
__device__ hf d_Woutb[VC * EC];
__device__ hf d_embb[(VC + 2) * EC];
__device__ hf d_Wih0b[GHC * (EC + HC)];
__device__ hf d_Wphb[HC * UC];
__device__ hf d_encOb[T1C * BB * UC];

__device__ __forceinline__ float tanha(float x) {
    float y; asm("tanh.approx.f32 %0, %1;" : "=f"(y) : "f"(x)); return y;
}
__device__ __forceinline__ float sigfast(float x) { return 0.5f * tanha(0.5f * x) + 0.5f; }

__device__ __forceinline__ void cpa16(void* dst, const void* src) {
    uint32_t d = (uint32_t)__cvta_generic_to_shared(dst);
    asm volatile("cp.async.cg.shared.global [%0], [%1], 16;\n" :: "r"(d), "l"(src));
}
__device__ __forceinline__ void cpa_commit() { asm volatile("cp.async.commit_group;\n"); }
template <int N> __device__ __forceinline__ void cpa_wait() {
    asm volatile("cp.async.wait_group %0;\n" :: "n"(N));
}

// ---------------- prologue kernels ----------------
__global__ void cvt_kernel(const float* __restrict__ src, hf* __restrict__ dst, int n4) {
    int i = blockIdx.x * blockDim.x + threadIdx.x;
    if (i >= n4) return;
    float4 v = ((const float4*)src)[i];
    hf2* d = (hf2*)dst + i * 2;
    d[0] = __floats2half2_rn(v.x, v.y);
    d[1] = __floats2half2_rn(v.z, v.w);
}

__global__ void wperm_kernel(const float* __restrict__ W, hf* __restrict__ dst, int ldw) {
    int idx = blockIdx.x * blockDim.x + threadIdx.x;
    if (idx >= GHC * ldw) return;
    int np = idx / ldw, c = idx - np * ldw;
    int h = np >> 2, gate = np & 3;
    dst[idx] = __float2half(W[(size_t)(gate * HC + h) * ldw + c]);
}

__global__ void w1catperm_kernel(const float* __restrict__ Wih1, const float* __restrict__ Whh1) {
    int idx = blockIdx.x * blockDim.x + threadIdx.x;
    if (idx >= GHC * 1024) return;
    int np = idx >> 10, c = idx & 1023;
    int o = (np & 3) * HC + (np >> 2);
    float v = (c < HC) ? Wih1[(size_t)o * HC + c] : Whh1[(size_t)o * HC + (c - HC)];
    d_W1catb[idx] = __float2half(v);
}

__global__ void biasperm_kernel(const float* __restrict__ bih0, const float* __restrict__ bhh0,
                                const float* __restrict__ bih1, const float* __restrict__ bhh1) {
    int idx = blockIdx.x * blockDim.x + threadIdx.x;
    if (idx >= GHC) return;
    int o = (idx & 3) * HC + (idx >> 2);
    d_b0p[idx] = bih0[o] + bhh0[o];
    d_b1p[idx] = bih1[o] + bhh1[o];
}

__global__ void tok_kernel(const int* __restrict__ prev) {
    int r = blockIdx.x * blockDim.x + threadIdx.x;
    if (r >= GIN_ROWS_PAD) return;
    if (r < GIN_ROWS) {
        int k = r / (BB * JC);
        int bj = r - k * (BB * JC);
        int b = bj / JC;
        int j = bj - b * JC;
        int pin = j + k - 1; if (pin > T2C - 1) pin = T2C - 1;
        int tin = (k == 0) ? START_ID : prev[b * T2C + pin];
        d_ginoff[r] = tin * EC;
        int pt = j + k; if (pt > T2C - 1) pt = T2C - 1;
        d_tgttok[r] = prev[b * T2C + pt];
    } else {
        d_ginoff[r] = 0;
    }
}

__global__ void ctxoff_kernel() {
    int r = threadIdx.x;
    if (r < 256) {
        int b = r / T1C, t1 = r - b * T1C;
        d_ctxoff[r] = t1 * (BB * UC) + b * UC;
    }
}

__global__ void hcinit_kernel(const float* __restrict__ ench, const float* __restrict__ encc,
                              const float* __restrict__ Wph, const float* __restrict__ bph,
                              const float* __restrict__ Wpc, const float* __restrict__ bpc) {
    int idx = blockIdx.x * blockDim.x + threadIdx.x;
    if (idx >= 2 * BB * HC) return;
    int l = idx / (BB * HC);
    int b = (idx / HC) % BB;
    int h = idx % HC;
    const float4* eh = (const float4*)(ench + l * BB * UC + b * UC);
    const float4* ec = (const float4*)(encc + l * BB * UC + b * UC);
    const float4* wh = (const float4*)(Wph + (size_t)h * UC);
    const float4* wc = (const float4*)(Wpc + (size_t)h * UC);
    float sh = 0.f, sc = 0.f;
    for (int u = 0; u < UC / 4; u++) {
        float4 a = eh[u], w = wh[u];
        sh += a.x * w.x + a.y * w.y + a.z * w.z + a.w * w.w;
        float4 a2 = ec[u], w2 = wc[u];
        sc += a2.x * w2.x + a2.y * w2.y + a2.z * w2.z + a2.w * w2.w;
    }
    d_hinit[idx] = sh + bph[h];
    d_cinit[idx] = sc + bpc[h];
}

__global__ void initX_kernel() {
    int idx = blockIdx.x * blockDim.x + threadIdx.x;
    if (idx >= NN * HC) return;
    int n = idx >> 9, h = idx & 511;
    int b = n / (T1C * JC);
    d_X1[(size_t)n * 1024 + h]       = __float2half(d_hinit[b * HC + h]);
    d_X1[(size_t)n * 1024 + 512 + h] = __float2half(d_hinit[BB * HC + b * HC + h]);
    d_c0[idx] = d_cinit[b * HC + h];
    d_c1[idx] = d_cinit[BB * HC + b * HC + h];
    if (h == 0) d_cum[n] = 0.f;
}

// ---------------- fp16 TN GEMM (f16 acc), 128x128 tile, 2-stage (R12 proven) ----------
// EPI: 0 none, 1 +e1[n], 4 CELL0 (+gin+gctx, cell), 5 CELL1 (+e1[n], cell)
#define SASTRIDE 40
#define CSTRIDE 136
#define GSM_BYTES 40960
template <int EPI, bool GATHER, bool OBF>
__launch_bounds__(256)
__global__ void gemm_hf(const hf* __restrict__ A, int lda,
                        const hf* __restrict__ Bm, int ldb,
                        void* __restrict__ Cv, int ldc, int K,
                        const int* __restrict__ rowoff,
                        const float* __restrict__ e1, const float* __restrict__ e2,
                        int kstep, float* __restrict__ cptr, hf* __restrict__ hout) {
    extern __shared__ char smraw[];
    hf* sA = (hf*)smraw;
    hf* sB = sA + 2 * 128 * SASTRIDE;
    hf* sC = (hf*)smraw;                      // 128 x 136 overlay

    int tid = threadIdx.x;
    int m0 = blockIdx.y * 128, n0 = blockIdx.x * 128;
    int wid = tid >> 5;
    int wm = wid & 1, wn = wid >> 1;          // warp tile 64(m) x 32(n)

    wmma::fragment<wmma::accumulator, 16, 16, 16, hf> acc[4][2];
#pragma unroll
    for (int mi = 0; mi < 4; mi++)
#pragma unroll
        for (int ni = 0; ni < 2; ni++) wmma::fill_fragment(acc[mi][ni], __float2half(0.0f));

    int nk = K >> 5;

#define GEMM_ISSUE(S)                                                                    \
    {                                                                                    \
        int buf_ = (S) & 1;                                                              \
        int k0_ = (S) << 5;                                                              \
        _Pragma("unroll")                                                                \
        for (int i_ = 0; i_ < 2; i_++) {                                                 \
            int idx_ = tid + i_ * 256;                                                   \
            int r_ = idx_ >> 2, c_ = idx_ & 3;                                           \
            const hf* src_ = GATHER ? (A + rowoff[m0 + r_] + k0_ + c_ * 8)               \
                                    : (A + (size_t)(m0 + r_) * lda + k0_ + c_ * 8);      \
            cpa16(sA + buf_ * (128 * SASTRIDE) + r_ * SASTRIDE + c_ * 8, src_);          \
        }                                                                                \
        _Pragma("unroll")                                                                \
        for (int i_ = 0; i_ < 2; i_++) {                                                 \
            int idx_ = tid + i_ * 256;                                                   \
            int r_ = idx_ >> 2, c_ = idx_ & 3;                                           \
            cpa16(sB + buf_ * (128 * SASTRIDE) + r_ * SASTRIDE + c_ * 8,                 \
                  Bm + (size_t)(n0 + r_) * ldb + k0_ + c_ * 8);                          \
        }                                                                                \
        cpa_commit();                                                                    \
    }

    GEMM_ISSUE(0);
    for (int s = 0; s < nk; s++) {
        cpa_wait<0>();
        __syncthreads();
        if (s + 1 < nk) GEMM_ISSUE(s + 1);
        int buf = s & 1;
        const hf* a_base = sA + buf * (128 * SASTRIDE);
        const hf* b_base = sB + buf * (128 * SASTRIDE);
#pragma unroll
        for (int kk = 0; kk < 2; kk++) {
            wmma::fragment<wmma::matrix_a, 16, 16, 16, hf, wmma::row_major> af[4];
            wmma::fragment<wmma::matrix_b, 16, 16, 16, hf, wmma::col_major> bfr[2];
#pragma unroll
            for (int mi = 0; mi < 4; mi++)
                wmma::load_matrix_sync(af[mi], a_base + (wm * 64 + mi * 16) * SASTRIDE + kk * 16, SASTRIDE);
#pragma unroll
            for (int ni = 0; ni < 2; ni++)
                wmma::load_matrix_sync(bfr[ni], b_base + (wn * 32 + ni * 16) * SASTRIDE + kk * 16, SASTRIDE);
#pragma unroll
            for (int mi = 0; mi < 4; mi++)
#pragma unroll
                for (int ni = 0; ni < 2; ni++)
                    wmma::mma_sync(acc[mi][ni], af[mi], bfr[ni], acc[mi][ni]);
        }
    }
    __syncthreads();
#pragma unroll
    for (int mi = 0; mi < 4; mi++)
#pragma unroll
        for (int ni = 0; ni < 2; ni++)
            wmma::store_matrix_sync(sC + (wm * 64 + mi * 16) * CSTRIDE + wn * 32 + ni * 16,
                                    acc[mi][ni], CSTRIDE, wmma::mem_row_major);
    __syncthreads();

#pragma unroll
    for (int i = 0; i < 16; i++) {
        int idx = tid + i * 256;
        int r = idx >> 5, c4 = idx & 31;
        uint2 raw = *(uint2*)(sC + r * CSTRIDE + c4 * 4);
        hf2 p0 = *(hf2*)&raw.x;
        hf2 p1 = *(hf2*)&raw.y;
        float4 v = make_float4(__low2float(p0), __high2float(p0),
                               __low2float(p1), __high2float(p1));
        int m = m0 + r;
        int nb = n0 + c4 * 4;
        if (EPI == 1 || EPI == 5) {
            float4 bb = *(const float4*)(e1 + nb);
            v.x += bb.x; v.y += bb.y; v.z += bb.z; v.w += bb.w;
        }
        if (EPI == 4) {
            int b = m / (T1C * JC);
            int rem = m - b * (T1C * JC);
            int t1 = rem / JC;
            int j = rem - t1 * JC;
            const float* gi = e1 + (size_t)((kstep * BB + b) * JC + j) * GHC + nb;
            const float* gc = e2 + (size_t)(b * T1C + t1) * GHC + nb;
            float4 a1 = *(const float4*)gi;
            float4 a2 = *(const float4*)gc;
            v.x += a1.x + a2.x; v.y += a1.y + a2.y; v.z += a1.z + a2.z; v.w += a1.w + a2.w;
        }
        if (EPI == 4 || EPI == 5) {
            int h = nb >> 2;
            size_t cix = (size_t)m * HC + h;
            float cold = cptr[cix];
            float cn = sigfast(v.y) * cold + sigfast(v.x) * tanha(v.z);
            cptr[cix] = cn;
            hout[(size_t)m * 1024 + h] = __float2half(sigfast(v.w) * tanha(cn));
        } else if (OBF) {
            hf2* p = (hf2*)((hf*)Cv + (size_t)m * ldc + nb);
            p[0] = __floats2half2_rn(v.x, v.y);
            p[1] = __floats2half2_rn(v.z, v.w);
        } else {
            *(float4*)((float*)Cv + (size_t)m * ldc + nb) = v;
        }
    }
#undef GEMM_ISSUE
}

// ---------------- fused Wout GEMM + LSE, software-pipelined (LSE lags MMA by 1 chunk) ----
#define WA_STRIDE 264
#define WB_STRIDE 264
#define WC_STRIDE 72
#define WOUT_SMEM_BYTES (64 * WA_STRIDE * 2 + 2 * 64 * WB_STRIDE * 2 + 2 * 64 * WC_STRIDE * 2 + 64 * 5 * 4)
__launch_bounds__(256)
__global__ void wout_lse(const hf* __restrict__ fco, const hf* __restrict__ Wout,
                         const float* __restrict__ bout, const int* __restrict__ tgttok,
                         float* __restrict__ cum, float* __restrict__ outp, int kstep) {
    extern __shared__ char smraw[];
    hf* A_s = (hf*)smraw;                            // 64 x 264
    hf* B_s = A_s + 64 * WA_STRIDE;                  // 2 x 64 x 264
    hf* C_s = B_s + 2 * 64 * WB_STRIDE;              // 2 x 64 x 72 (double-buffered)
    float* rM = (float*)(C_s + 2 * 64 * WC_STRIDE);
    float* rS = rM + 64;
    float* rE = rS + 64;
    float* rT = rE + 64;
    int* rTgt = (int*)(rT + 64);

    int tid = threadIdx.x;
    int m0 = blockIdx.x * 64;

#pragma unroll
    for (int i = 0; i < 8; i++) {        // A: 64 x 256 halves
        int idx = tid + i * 256;
        int r = idx >> 5, c = idx & 31;
        *(uint4*)(A_s + r * WA_STRIDE + c * 8) = *(const uint4*)(fco + (size_t)(m0 + r) * EC + c * 8);
    }
    if (tid < 64) {
        int n = m0 + tid;
        int b = n / (T1C * JC);
        int rem = n - b * (T1C * JC);
        int j = rem % JC;
        rTgt[tid] = tgttok[(kstep * BB + b) * JC + j];
        rM[tid] = -1e30f; rS[tid] = 0.f; rE[tid] = 0.f; rT[tid] = 0.f;
    }

    int wid = tid >> 5;
    int wm = wid & 1, wn = wid >> 1;     // warp tile 32(m) x 16(n)
    int rr = tid >> 2, qq = tid & 3;     // LSE lane mapping: 4 lanes per row
    int tgt = rTgt[rr];                  // read AFTER first __syncthreads below (see note)

#define WOUT_ISSUE(S)                                                                  \
    {                                                                                  \
        int buf_ = (S) & 1;                                                            \
        _Pragma("unroll")                                                              \
        for (int i_ = 0; i_ < 8; i_++) {                                               \
            int idx_ = tid + i_ * 256;                                                 \
            int r_ = idx_ >> 5, c_ = idx_ & 31;                                        \
            cpa16(B_s + buf_ * (64 * WB_STRIDE) + r_ * WB_STRIDE + c_ * 8,             \
                  Wout + (size_t)((S) * 64 + r_) * EC + c_ * 8);                       \
        }                                                                              \
        cpa_commit();                                                                  \
    }

    // LSE scan over chunk NCIDX stored in C buffer CB
#define LSE_CHUNK(NCIDX, CB)                                                           \
    {                                                                                  \
        int n0v = (NCIDX) * 64;                                                        \
        const hf* cb_ = C_s + (CB) * (64 * WC_STRIDE);                                 \
        float lv[16];                                                                  \
        float lm = -1e30f;                                                             \
        _Pragma("unroll")                                                              \
        for (int c = 0; c < 16; c++) {                                                 \
            int col = qq * 16 + c;                                                     \
            int gcol = n0v + col;                                                      \
            float l = __half2float(cb_[rr * WC_STRIDE + col]) + bout[gcol];            \
            lv[c] = l;                                                                 \
            lm = fmaxf(lm, l);                                                         \
            if (gcol == 2) rE[rr] = l;                                                 \
            if (gcol == tgt) rT[rr] = l;                                               \
        }                                                                              \
        float ls = 0.f;                                                                \
        _Pragma("unroll")                                                              \
        for (int c = 0; c < 16; c++) ls += __expf(lv[c] - lm);                         \
        _Pragma("unroll")                                                              \
        for (int off = 1; off < 4; off <<= 1) {                                        \
            float om = __shfl_xor_sync(0xffffffffu, lm, off);                          \
            float os = __shfl_xor_sync(0xffffffffu, ls, off);                          \
            float nm = fmaxf(lm, om);                                                  \
            ls = ls * __expf(lm - nm) + os * __expf(om - nm);                          \
            lm = nm;                                                                   \
        }                                                                              \
        if (qq == 0) {                                                                 \
            float M = rM[rr], S = rS[rr];                                              \
            float nm = fmaxf(M, lm);                                                   \
            rS[rr] = S * __expf(M - nm) + ls * __expf(lm - nm);                        \
            rM[rr] = nm;                                                               \
        }                                                                              \
    }

    WOUT_ISSUE(0);
    const int NCC = VC / 64;   // 125
    for (int nc = 0; nc < NCC; nc++) {
        cpa_wait<0>();
        __syncthreads();                 // B(nc) ready; C stores of nc-1 visible
        if (nc == 0) tgt = rTgt[rr];     // rTgt written before this first sync
        if (nc + 1 < NCC) WOUT_ISSUE(nc + 1);
        int buf = nc & 1;
        const hf* b_base = B_s + buf * (64 * WB_STRIDE);

        wmma::fragment<wmma::accumulator, 16, 16, 16, hf> acc[2];
        wmma::fill_fragment(acc[0], __float2half(0.0f));
        wmma::fill_fragment(acc[1], __float2half(0.0f));
#pragma unroll
        for (int kk = 0; kk < 16; kk++) {
            wmma::fragment<wmma::matrix_a, 16, 16, 16, hf, wmma::row_major> af[2];
            wmma::fragment<wmma::matrix_b, 16, 16, 16, hf, wmma::col_major> bfr;
            wmma::load_matrix_sync(af[0], A_s + (wm * 32) * WA_STRIDE + kk * 16, WA_STRIDE);
            wmma::load_matrix_sync(af[1], A_s + (wm * 32 + 16) * WA_STRIDE + kk * 16, WA_STRIDE);
            wmma::load_matrix_sync(bfr, b_base + (wn * 16) * WB_STRIDE + kk * 16, WB_STRIDE);
            wmma::mma_sync(acc[0], af[0], bfr, acc[0]);
            wmma::mma_sync(acc[1], af[1], bfr, acc[1]);
        }
        // LSE of previous chunk overlaps with tensor-pipe drain of this chunk
        if (nc > 0) LSE_CHUNK(nc - 1, (nc - 1) & 1);
        // store this chunk's result into its C buffer (read by LSE next iteration)
        wmma::store_matrix_sync(C_s + buf * (64 * WC_STRIDE) + (wm * 32) * WC_STRIDE + wn * 16,
                                acc[0], WC_STRIDE, wmma::mem_row_major);
        wmma::store_matrix_sync(C_s + buf * (64 * WC_STRIDE) + (wm * 32 + 16) * WC_STRIDE + wn * 16,
                                acc[1], WC_STRIDE, wmma::mem_row_major);
    }
    __syncthreads();
    LSE_CHUNK(NCC - 1, (NCC - 1) & 1);
    __syncthreads();

    if (tid < 64) {
        int n = m0 + tid;
        float lse = rM[tid] + logf(rS[tid]);
        int j = n % JC;
        bool valid = (j + kstep) <= T2C;
        float cv = cum[n];
        outp[(size_t)n * KSEG + kstep] = valid ? (cv + rE[tid] - lse) : -1e9f;
        cum[n] = cv + rT[tid] - lse;
    }
#undef WOUT_ISSUE
#undef LSE_CHUNK
}

// ---------------- host launch ----------------
static inline float* fsym(const void* sym) {
    void* p = nullptr; cudaGetSymbolAddress(&p, sym); return (float*)p;
}
static inline hf* hsym(const void* sym) {
    void* p = nullptr; cudaGetSymbolAddress(&p, sym); return (hf*)p;
}
static inline int* isym(const void* sym) {
    void* p = nullptr; cudaGetSymbolAddress(&p, sym); return (int*)p;
}

extern "C" void kernel_launch(void* const* d_in, const int* in_sizes, int n_in,
                              void* d_out, int out_size) {
    const int*   prev   = (const int*)d_in[0];
    const float* encO   = (const float*)d_in[1];
    const float* encH   = (const float*)d_in[2];
    const float* encC   = (const float*)d_in[3];
    const float* embed  = (const float*)d_in[4];
    const float* Wph    = (const float*)d_in[5];
    const float* bph    = (const float*)d_in[6];
    const float* Wpc    = (const float*)d_in[7];
    const float* bpc    = (const float*)d_in[8];
    const float* Wih0   = (const float*)d_in[9];
    const float* Whh0   = (const float*)d_in[10];
    const float* bih0   = (const float*)d_in[11];
    const float* bhh0   = (const float*)d_in[12];
    const float* Wih1   = (const float*)d_in[13];
    const float* Whh1   = (const float*)d_in[14];
    const float* bih1   = (const float*)d_in[15];
    const float* bhh1   = (const float*)d_in[16];
    const float* Wfc    = (const float*)d_in[17];
    const float* bfc    = (const float*)d_in[18];
    const float* Wout   = (const float*)d_in[19];
    const float* bout   = (const float*)d_in[20];
    float* outp = (float*)d_out;

    hf*    pX1   = hsym(d_X1);
    float* pc0   = fsym(d_c0);
    float* pc1   = fsym(d_c1);
    hf*    pfco  = hsym(d_fco);
    float* pgin  = fsym(d_gin);
    float* pgctx = fsym(d_gctx);
    hf*    pctxb = hsym(d_ctxb);
    float* pcum  = fsym(d_cum);
    float* pb0p  = fsym(d_b0p);
    float* pb1p  = fsym(d_b1p);
    int*   pgoff = isym(d_ginoff);
    int*   pcoff = isym(d_ctxoff);
    int*   ptgt  = isym(d_tgttok);
    hf*    pWhh0b  = hsym(d_Whh0b);
    hf*    pW1catb = hsym(d_W1catb);
    hf*    pWfcb   = hsym(d_Wfcb);
    hf*    pWoutb  = hsym(d_Woutb);
    hf*    pembb   = hsym(d_embb);
    hf*    pWih0b  = hsym(d_Wih0b);
    hf*    pWphb   = hsym(d_Wphb);
    hf*    pencOb  = hsym(d_encOb);

    // one-time stream/event setup (topology identical every capture)
    static bool s_init = false;
    static cudaStream_t sW;
    static cudaEvent_t evG1[KSEG], evFc[KSEG], evW[KSEG];
    if (!s_init) {
        cudaStreamCreateWithFlags(&sW, cudaStreamNonBlocking);
        for (int i = 0; i < KSEG; i++) {
            cudaEventCreateWithFlags(&evG1[i], cudaEventDisableTiming);
            cudaEventCreateWithFlags(&evFc[i], cudaEventDisableTiming);
            cudaEventCreateWithFlags(&evW[i], cudaEventDisableTiming);
        }
        s_init = true;
    }

    cudaFuncSetAttribute(gemm_hf<0, true,  false>, cudaFuncAttributeMaxDynamicSharedMemorySize, GSM_BYTES);
    cudaFuncSetAttribute(gemm_hf<1, true,  true >, cudaFuncAttributeMaxDynamicSharedMemorySize, GSM_BYTES);
    cudaFuncSetAttribute(gemm_hf<1, false, false>, cudaFuncAttributeMaxDynamicSharedMemorySize, GSM_BYTES);
    cudaFuncSetAttribute(gemm_hf<1, false, true >, cudaFuncAttributeMaxDynamicSharedMemorySize, GSM_BYTES);
    cudaFuncSetAttribute(gemm_hf<4, false, false>, cudaFuncAttributeMaxDynamicSharedMemorySize, GSM_BYTES);
    cudaFuncSetAttribute(gemm_hf<5, false, false>, cudaFuncAttributeMaxDynamicSharedMemorySize, GSM_BYTES);
    cudaFuncSetAttribute(wout_lse, cudaFuncAttributeMaxDynamicSharedMemorySize, WOUT_SMEM_BYTES);

    // ---- prologue: conversions / permutations ----
    wperm_kernel<<<(GHC * HC + 255) / 256, 256>>>(Whh0, pWhh0b, HC);
    w1catperm_kernel<<<(GHC * 1024 + 255) / 256, 256>>>(Wih1, Whh1);
    wperm_kernel<<<(GHC * (EC + HC) + 255) / 256, 256>>>(Wih0, pWih0b, EC + HC);
    biasperm_kernel<<<(GHC + 255) / 256, 256>>>(bih0, bhh0, bih1, bhh1);
    cvt_kernel<<<(EC * HC / 4 + 255) / 256, 256>>>(Wfc, pWfcb, EC * HC / 4);
    cvt_kernel<<<(VC * EC / 4 + 255) / 256, 256>>>(Wout, pWoutb, VC * EC / 4);
    cvt_kernel<<<((VC + 2) * EC / 4 + 255) / 256, 256>>>(embed, pembb, (VC + 2) * EC / 4);
    cvt_kernel<<<(HC * UC / 4 + 255) / 256, 256>>>(Wph, pWphb, HC * UC / 4);
    cvt_kernel<<<(T1C * BB * UC / 4 + 255) / 256, 256>>>(encO, pencOb, T1C * BB * UC / 4);

    tok_kernel<<<(GIN_ROWS_PAD + 255) / 256, 256>>>(prev);
    ctxoff_kernel<<<1, 256>>>();
    hcinit_kernel<<<(2 * BB * HC + 255) / 256, 256>>>(encH, encC, Wph, bph, Wpc, bpc);
    initX_kernel<<<(NN * HC) / 256, 256>>>();

    // ctx(fp16) = encO @ Wph^T + bph : M=256, N=512, K=1024 (gather A)
    gemm_hf<1, true, true><<<dim3(512 / 128, 256 / 128), 256, GSM_BYTES>>>(
        pencOb, 0, pWphb, UC, pctxb, HC, UC, pcoff, bph, nullptr, 0, nullptr, nullptr);
    // gctx = ctx @ Wih0p[:,E:]^T + b0p : M=256, N=2048(perm), K=512
    gemm_hf<1, false, false><<<dim3(GHC / 128, 256 / 128), 256, GSM_BYTES>>>(
        pctxb, HC, pWih0b + EC, EC + HC, pgctx, GHC, HC, nullptr, pb0p, nullptr, 0, nullptr, nullptr);
    // gin = emb @ Wih0p[:, :E]^T : M=2432, N=2048(perm), K=256 (gather A)
    gemm_hf<0, true, false><<<dim3(GHC / 128, GIN_ROWS_PAD / 128), 256, GSM_BYTES>>>(
        pembb, 0, pWih0b, EC + HC, pgin, GHC, EC, pgoff, nullptr, nullptr, 0, nullptr, nullptr);

    for (int k = 0; k < KSEG; k++) {
        hf* fcobuf = pfco + (size_t)(k & 1) * NN * EC;
        // layer 0 (s0): g0 = h0 @ Whh0p^T + gin + gctx, fused cell -> c0, h0.
        gemm_hf<4, false, false><<<dim3(GHC / 128, NN / 128), 256, GSM_BYTES>>>(
            pX1, 1024, pWhh0b, HC, nullptr, 0, HC, nullptr, pgin, pgctx, k, pc0, pX1);
        // layer 1 (s0): writes h1 — wait until fc(k-1) finished READING h1.
        if (k >= 1) cudaStreamWaitEvent(0, evFc[k - 1], 0);
        gemm_hf<5, false, false><<<dim3(GHC / 128, NN / 128), 256, GSM_BYTES>>>(
            pX1, 1024, pW1catb, 1024, nullptr, 0, 1024, nullptr, pb1p, nullptr, k, pc1, pX1 + 512);
        cudaEventRecord(evG1[k], 0);

        // fc(k) + wout(k) on side stream (fco buffer reuse ordered by sW FIFO)
        cudaStreamWaitEvent(sW, evG1[k], 0);
        gemm_hf<1, false, true><<<dim3(EC / 128, NN / 128), 256, GSM_BYTES, sW>>>(
            pX1 + 512, 1024, pWfcb, HC, fcobuf, EC, HC, nullptr, bfc, nullptr, 0, nullptr, nullptr);
        cudaEventRecord(evFc[k], sW);
        wout_lse<<<NN / 64, 256, WOUT_SMEM_BYTES, sW>>>(fcobuf, pWoutb, bout, ptgt, pcum, outp, k);
        cudaEventRecord(evW[k], sW);
    }
    // graph sink must depend on the last wout
    cudaStreamWaitEvent(0, evW[KSEG - 1], 0);
}

// round 15
// speedup vs baseline: 1.1473x; 1.1473x over previous
#include <cuda_runtime.h>
#include <cuda_fp16.h>
#include <mma.h>
#include <math.h>
#include <stdint.h>

using namespace nvcuda;

// ---------------- problem constants ----------------
#define BB 8
#define T1C 32
#define T2C 32
#define JC 33
#define KSEG 9
#define NN 8448
#define EC 256
#define HC 512
#define UC 1024
#define GHC 2048
#define VC 8000
#define START_ID 8001
#define GIN_ROWS 2376
#define GIN_ROWS_PAD 2432

typedef __half hf;
typedef __half2 hf2;

// ---------------- device scratch ----------------
__device__ hf    d_X1[NN * 1024];             // [h0 | h1] per row (fp16)
__device__ float d_c0[NN * HC];
__device__ float d_c1[NN * HC];
__device__ hf    d_fco[2 * NN * EC];          // double-buffered across steps
__device__ float d_gin[GIN_ROWS_PAD * GHC];
__device__ float d_gctx[256 * GHC];
__device__ hf    d_ctxb[256 * HC];
__device__ float d_hinit[2 * BB * HC];
__device__ float d_cinit[2 * BB * HC];
__device__ float d_cum[NN];
__device__ float d_b0p[GHC];
__device__ float d_b1p[GHC];
__device__ int   d_ginoff[GIN_ROWS_PAD];
__device__ int   d_ctxoff[256];
__device__ int   d_tgttok[GIN_ROWS];
__device__ hf d_Whh0b[GHC * HC];
__device__ hf d_W1catb[GHC * 1024];
__device__ hf d_Wfcb[EC * HC];
__device__ hf d_Woutb[VC * EC];
__device__ hf d_embb[(VC + 2) * EC];
__device__ hf d_Wih0b[GHC * (EC + HC)];
__device__ hf d_Wphb[HC * UC];
__device__ hf d_encOb[T1C * BB * UC];

__device__ __forceinline__ float tanha(float x) {
    float y; asm("tanh.approx.f32 %0, %1;" : "=f"(y) : "f"(x)); return y;
}
__device__ __forceinline__ float sigfast(float x) { return 0.5f * tanha(0.5f * x) + 0.5f; }

__device__ __forceinline__ void cpa16(void* dst, const void* src) {
    uint32_t d = (uint32_t)__cvta_generic_to_shared(dst);
    asm volatile("cp.async.cg.shared.global [%0], [%1], 16;\n" :: "r"(d), "l"(src));
}
__device__ __forceinline__ void cpa_commit() { asm volatile("cp.async.commit_group;\n"); }
template <int N> __device__ __forceinline__ void cpa_wait() {
    asm volatile("cp.async.wait_group %0;\n" :: "n"(N));
}

// ---------------- prologue kernels ----------------
__global__ void cvt_kernel(const float* __restrict__ src, hf* __restrict__ dst, int n4) {
    int i = blockIdx.x * blockDim.x + threadIdx.x;
    if (i >= n4) return;
    float4 v = ((const float4*)src)[i];
    hf2* d = (hf2*)dst + i * 2;
    d[0] = __floats2half2_rn(v.x, v.y);
    d[1] = __floats2half2_rn(v.z, v.w);
}

__global__ void wperm_kernel(const float* __restrict__ W, hf* __restrict__ dst, int ldw) {
    int idx = blockIdx.x * blockDim.x + threadIdx.x;
    if (idx >= GHC * ldw) return;
    int np = idx / ldw, c = idx - np * ldw;
    int h = np >> 2, gate = np & 3;
    dst[idx] = __float2half(W[(size_t)(gate * HC + h) * ldw + c]);
}

__global__ void w1catperm_kernel(const float* __restrict__ Wih1, const float* __restrict__ Whh1) {
    int idx = blockIdx.x * blockDim.x + threadIdx.x;
    if (idx >= GHC * 1024) return;
    int np = idx >> 10, c = idx & 1023;
    int o = (np & 3) * HC + (np >> 2);
    float v = (c < HC) ? Wih1[(size_t)o * HC + c] : Whh1[(size_t)o * HC + (c - HC)];
    d_W1catb[idx] = __float2half(v);
}

__global__ void biasperm_kernel(const float* __restrict__ bih0, const float* __restrict__ bhh0,
                                const float* __restrict__ bih1, const float* __restrict__ bhh1) {
    int idx = blockIdx.x * blockDim.x + threadIdx.x;
    if (idx >= GHC) return;
    int o = (idx & 3) * HC + (idx >> 2);
    d_b0p[idx] = bih0[o] + bhh0[o];
    d_b1p[idx] = bih1[o] + bhh1[o];
}

__global__ void tok_kernel(const int* __restrict__ prev) {
    int r = blockIdx.x * blockDim.x + threadIdx.x;
    if (r >= GIN_ROWS_PAD) return;
    if (r < GIN_ROWS) {
        int k = r / (BB * JC);
        int bj = r - k * (BB * JC);
        int b = bj / JC;
        int j = bj - b * JC;
        int pin = j + k - 1; if (pin > T2C - 1) pin = T2C - 1;
        int tin = (k == 0) ? START_ID : prev[b * T2C + pin];
        d_ginoff[r] = tin * EC;
        int pt = j + k; if (pt > T2C - 1) pt = T2C - 1;
        d_tgttok[r] = prev[b * T2C + pt];
    } else {
        d_ginoff[r] = 0;
    }
}

__global__ void ctxoff_kernel() {
    int r = threadIdx.x;
    if (r < 256) {
        int b = r / T1C, t1 = r - b * T1C;
        d_ctxoff[r] = t1 * (BB * UC) + b * UC;
    }
}

__global__ void hcinit_kernel(const float* __restrict__ ench, const float* __restrict__ encc,
                              const float* __restrict__ Wph, const float* __restrict__ bph,
                              const float* __restrict__ Wpc, const float* __restrict__ bpc) {
    int idx = blockIdx.x * blockDim.x + threadIdx.x;
    if (idx >= 2 * BB * HC) return;
    int l = idx / (BB * HC);
    int b = (idx / HC) % BB;
    int h = idx % HC;
    const float4* eh = (const float4*)(ench + l * BB * UC + b * UC);
    const float4* ec = (const float4*)(encc + l * BB * UC + b * UC);
    const float4* wh = (const float4*)(Wph + (size_t)h * UC);
    const float4* wc = (const float4*)(Wpc + (size_t)h * UC);
    float sh = 0.f, sc = 0.f;
    for (int u = 0; u < UC / 4; u++) {
        float4 a = eh[u], w = wh[u];
        sh += a.x * w.x + a.y * w.y + a.z * w.z + a.w * w.w;
        float4 a2 = ec[u], w2 = wc[u];
        sc += a2.x * w2.x + a2.y * w2.y + a2.z * w2.z + a2.w * w2.w;
    }
    d_hinit[idx] = sh + bph[h];
    d_cinit[idx] = sc + bpc[h];
}

__global__ void initX_kernel() {
    int idx = blockIdx.x * blockDim.x + threadIdx.x;
    if (idx >= NN * HC) return;
    int n = idx >> 9, h = idx & 511;
    int b = n / (T1C * JC);
    d_X1[(size_t)n * 1024 + h]       = __float2half(d_hinit[b * HC + h]);
    d_X1[(size_t)n * 1024 + 512 + h] = __float2half(d_hinit[BB * HC + b * HC + h]);
    d_c0[idx] = d_cinit[b * HC + h];
    d_c1[idx] = d_cinit[BB * HC + b * HC + h];
    if (h == 0) d_cum[n] = 0.f;
}

// ---------------- fp16 TN GEMM (f16 acc), 128x128 tile, 2-stage (R12 proven) ----------
// EPI: 0 none, 1 +e1[n], 4 CELL0 (+gin+gctx, cell), 5 CELL1 (+e1[n], cell)
#define SASTRIDE 40
#define CSTRIDE 136
#define GSM_BYTES 40960
template <int EPI, bool GATHER, bool OBF>
__launch_bounds__(256)
__global__ void gemm_hf(const hf* __restrict__ A, int lda,
                        const hf* __restrict__ Bm, int ldb,
                        void* __restrict__ Cv, int ldc, int K,
                        const int* __restrict__ rowoff,
                        const float* __restrict__ e1, const float* __restrict__ e2,
                        int kstep, float* __restrict__ cptr, hf* __restrict__ hout) {
    extern __shared__ char smraw[];
    hf* sA = (hf*)smraw;
    hf* sB = sA + 2 * 128 * SASTRIDE;
    hf* sC = (hf*)smraw;                      // 128 x 136 overlay

    int tid = threadIdx.x;
    int m0 = blockIdx.y * 128, n0 = blockIdx.x * 128;
    int wid = tid >> 5;
    int wm = wid & 1, wn = wid >> 1;          // warp tile 64(m) x 32(n)

    wmma::fragment<wmma::accumulator, 16, 16, 16, hf> acc[4][2];
#pragma unroll
    for (int mi = 0; mi < 4; mi++)
#pragma unroll
        for (int ni = 0; ni < 2; ni++) wmma::fill_fragment(acc[mi][ni], __float2half(0.0f));

    int nk = K >> 5;

#define GEMM_ISSUE(S)                                                                    \
    {                                                                                    \
        int buf_ = (S) & 1;                                                              \
        int k0_ = (S) << 5;                                                              \
        _Pragma("unroll")                                                                \
        for (int i_ = 0; i_ < 2; i_++) {                                                 \
            int idx_ = tid + i_ * 256;                                                   \
            int r_ = idx_ >> 2, c_ = idx_ & 3;                                           \
            const hf* src_ = GATHER ? (A + rowoff[m0 + r_] + k0_ + c_ * 8)               \
                                    : (A + (size_t)(m0 + r_) * lda + k0_ + c_ * 8);      \
            cpa16(sA + buf_ * (128 * SASTRIDE) + r_ * SASTRIDE + c_ * 8, src_);          \
        }                                                                                \
        _Pragma("unroll")                                                                \
        for (int i_ = 0; i_ < 2; i_++) {                                                 \
            int idx_ = tid + i_ * 256;                                                   \
            int r_ = idx_ >> 2, c_ = idx_ & 3;                                           \
            cpa16(sB + buf_ * (128 * SASTRIDE) + r_ * SASTRIDE + c_ * 8,                 \
                  Bm + (size_t)(n0 + r_) * ldb + k0_ + c_ * 8);                          \
        }                                                                                \
        cpa_commit();                                                                    \
    }

    GEMM_ISSUE(0);
    for (int s = 0; s < nk; s++) {
        cpa_wait<0>();
        __syncthreads();
        if (s + 1 < nk) GEMM_ISSUE(s + 1);
        int buf = s & 1;
        const hf* a_base = sA + buf * (128 * SASTRIDE);
        const hf* b_base = sB + buf * (128 * SASTRIDE);
#pragma unroll
        for (int kk = 0; kk < 2; kk++) {
            wmma::fragment<wmma::matrix_a, 16, 16, 16, hf, wmma::row_major> af[4];
            wmma::fragment<wmma::matrix_b, 16, 16, 16, hf, wmma::col_major> bfr[2];
#pragma unroll
            for (int mi = 0; mi < 4; mi++)
                wmma::load_matrix_sync(af[mi], a_base + (wm * 64 + mi * 16) * SASTRIDE + kk * 16, SASTRIDE);
#pragma unroll
            for (int ni = 0; ni < 2; ni++)
                wmma::load_matrix_sync(bfr[ni], b_base + (wn * 32 + ni * 16) * SASTRIDE + kk * 16, SASTRIDE);
#pragma unroll
            for (int mi = 0; mi < 4; mi++)
#pragma unroll
                for (int ni = 0; ni < 2; ni++)
                    wmma::mma_sync(acc[mi][ni], af[mi], bfr[ni], acc[mi][ni]);
        }
    }
    __syncthreads();
#pragma unroll
    for (int mi = 0; mi < 4; mi++)
#pragma unroll
        for (int ni = 0; ni < 2; ni++)
            wmma::store_matrix_sync(sC + (wm * 64 + mi * 16) * CSTRIDE + wn * 32 + ni * 16,
                                    acc[mi][ni], CSTRIDE, wmma::mem_row_major);
    __syncthreads();

#pragma unroll
    for (int i = 0; i < 16; i++) {
        int idx = tid + i * 256;
        int r = idx >> 5, c4 = idx & 31;
        uint2 raw = *(uint2*)(sC + r * CSTRIDE + c4 * 4);
        hf2 p0 = *(hf2*)&raw.x;
        hf2 p1 = *(hf2*)&raw.y;
        float4 v = make_float4(__low2float(p0), __high2float(p0),
                               __low2float(p1), __high2float(p1));
        int m = m0 + r;
        int nb = n0 + c4 * 4;
        if (EPI == 1 || EPI == 5) {
            float4 bb = *(const float4*)(e1 + nb);
            v.x += bb.x; v.y += bb.y; v.z += bb.z; v.w += bb.w;
        }
        if (EPI == 4) {
            int b = m / (T1C * JC);
            int rem = m - b * (T1C * JC);
            int t1 = rem / JC;
            int j = rem - t1 * JC;
            const float* gi = e1 + (size_t)((kstep * BB + b) * JC + j) * GHC + nb;
            const float* gc = e2 + (size_t)(b * T1C + t1) * GHC + nb;
            float4 a1 = *(const float4*)gi;
            float4 a2 = *(const float4*)gc;
            v.x += a1.x + a2.x; v.y += a1.y + a2.y; v.z += a1.z + a2.z; v.w += a1.w + a2.w;
        }
        if (EPI == 4 || EPI == 5) {
            int h = nb >> 2;
            size_t cix = (size_t)m * HC + h;
            float cold = cptr[cix];
            float cn = sigfast(v.y) * cold + sigfast(v.x) * tanha(v.z);
            cptr[cix] = cn;
            hout[(size_t)m * 1024 + h] = __float2half(sigfast(v.w) * tanha(cn));
        } else if (OBF) {
            hf2* p = (hf2*)((hf*)Cv + (size_t)m * ldc + nb);
            p[0] = __floats2half2_rn(v.x, v.y);
            p[1] = __floats2half2_rn(v.z, v.w);
        } else {
            *(float4*)((float*)Cv + (size_t)m * ldc + nb) = v;
        }
    }
#undef GEMM_ISSUE
}

// ---------------- fused Wout GEMM + online LSE; A fragments cached in registers ------
// warp tile 16(m) x 32(n): wm = wid>>1 (4 m-tiles), wn = wid&1 (2 n-halves of 32)
#define WA_STRIDE 264
#define WB_STRIDE 264
#define WC_STRIDE 72
#define WOUT_SMEM_BYTES (64 * WA_STRIDE * 2 + 2 * 64 * WB_STRIDE * 2 + 64 * WC_STRIDE * 2 + 64 * 5 * 4)
__launch_bounds__(256)
__global__ void wout_lse(const hf* __restrict__ fco, const hf* __restrict__ Wout,
                         const float* __restrict__ bout, const int* __restrict__ tgttok,
                         float* __restrict__ cum, float* __restrict__ outp, int kstep) {
    extern __shared__ char smraw[];
    hf* A_s = (hf*)smraw;                            // 64 x 264
    hf* B_s = A_s + 64 * WA_STRIDE;                  // 2 x 64 x 264
    hf* C_s = B_s + 2 * 64 * WB_STRIDE;              // 64 x 72
    float* rM = (float*)(C_s + 64 * WC_STRIDE);
    float* rS = rM + 64;
    float* rE = rS + 64;
    float* rT = rE + 64;
    int* rTgt = (int*)(rT + 64);

    int tid = threadIdx.x;
    int m0 = blockIdx.x * 64;

#pragma unroll
    for (int i = 0; i < 8; i++) {        // A: 64 x 256 halves
        int idx = tid + i * 256;
        int r = idx >> 5, c = idx & 31;
        *(uint4*)(A_s + r * WA_STRIDE + c * 8) = *(const uint4*)(fco + (size_t)(m0 + r) * EC + c * 8);
    }
    if (tid < 64) {
        int n = m0 + tid;
        int b = n / (T1C * JC);
        int rem = n - b * (T1C * JC);
        int j = rem % JC;
        rTgt[tid] = tgttok[(kstep * BB + b) * JC + j];
        rM[tid] = -1e30f; rS[tid] = 0.f; rE[tid] = 0.f; rT[tid] = 0.f;
    }

    int wid = tid >> 5;
    int wm = wid >> 1, wn = wid & 1;     // warp tile 16(m) x 32(n)

#define WOUT_ISSUE(S)                                                                  \
    {                                                                                  \
        int buf_ = (S) & 1;                                                            \
        _Pragma("unroll")                                                              \
        for (int i_ = 0; i_ < 8; i_++) {                                               \
            int idx_ = tid + i_ * 256;                                                 \
            int r_ = idx_ >> 5, c_ = idx_ & 31;                                        \
            cpa16(B_s + buf_ * (64 * WB_STRIDE) + r_ * WB_STRIDE + c_ * 8,             \
                  Wout + (size_t)((S) * 64 + r_) * EC + c_ * 8);                       \
        }                                                                              \
        cpa_commit();                                                                  \
    }

    WOUT_ISSUE(0);
    __syncthreads();   // A_s + rTgt visible

    // cache the warp's 16 A fragments (one per kk) in registers — reused for all 125 chunks
    wmma::fragment<wmma::matrix_a, 16, 16, 16, hf, wmma::row_major> afc[16];
#pragma unroll
    for (int kk = 0; kk < 16; kk++)
        wmma::load_matrix_sync(afc[kk], A_s + (wm * 16) * WA_STRIDE + kk * 16, WA_STRIDE);

    const int NCC = VC / 64;
    for (int nc = 0; nc < NCC; nc++) {
        cpa_wait<0>();
        __syncthreads();                 // B(nc) ready; C_s free (LSE of nc-1 done)
        if (nc + 1 < NCC) WOUT_ISSUE(nc + 1);
        int buf = nc & 1;
        const hf* b_base = B_s + buf * (64 * WB_STRIDE);

        wmma::fragment<wmma::accumulator, 16, 16, 16, hf> acc[2];
        wmma::fill_fragment(acc[0], __float2half(0.0f));
        wmma::fill_fragment(acc[1], __float2half(0.0f));
#pragma unroll
        for (int kk = 0; kk < 16; kk++) {
            wmma::fragment<wmma::matrix_b, 16, 16, 16, hf, wmma::col_major> bfr;
            wmma::load_matrix_sync(bfr, b_base + (wn * 32) * WB_STRIDE + kk * 16, WB_STRIDE);
            wmma::mma_sync(acc[0], afc[kk], bfr, acc[0]);
            wmma::load_matrix_sync(bfr, b_base + (wn * 32 + 16) * WB_STRIDE + kk * 16, WB_STRIDE);
            wmma::mma_sync(acc[1], afc[kk], bfr, acc[1]);
        }
        wmma::store_matrix_sync(C_s + (wm * 16) * WC_STRIDE + wn * 32, acc[0], WC_STRIDE, wmma::mem_row_major);
        wmma::store_matrix_sync(C_s + (wm * 16) * WC_STRIDE + wn * 32 + 16, acc[1], WC_STRIDE, wmma::mem_row_major);
        __syncthreads();

        {   // online LSE over this 64-col chunk: 4 lanes per row, 16 cols each
            int n0v = nc * 64;
            int r = tid >> 2, q = tid & 3;
            int tgt = rTgt[r];
            float lv[16];
            float lm = -1e30f;
#pragma unroll
            for (int c = 0; c < 16; c++) {
                int col = q * 16 + c;
                int gcol = n0v + col;
                float l = __half2float(C_s[r * WC_STRIDE + col]) + bout[gcol];
                lv[c] = l;
                lm = fmaxf(lm, l);
                if (gcol == 2) rE[r] = l;
                if (gcol == tgt) rT[r] = l;
            }
            float ls = 0.f;
#pragma unroll
            for (int c = 0; c < 16; c++) ls += __expf(lv[c] - lm);
#pragma unroll
            for (int off = 1; off < 4; off <<= 1) {
                float om = __shfl_xor_sync(0xffffffffu, lm, off);
                float os = __shfl_xor_sync(0xffffffffu, ls, off);
                float nm = fmaxf(lm, om);
                ls = ls * __expf(lm - nm) + os * __expf(om - nm);
                lm = nm;
            }
            if (q == 0) {
                float M = rM[r], S = rS[r];
                float nm = fmaxf(M, lm);
                rS[r] = S * __expf(M - nm) + ls * __expf(lm - nm);
                rM[r] = nm;
            }
        }
        __syncthreads();
    }

    if (tid < 64) {
        int n = m0 + tid;
        float lse = rM[tid] + logf(rS[tid]);
        int j = n % JC;
        bool valid = (j + kstep) <= T2C;
        float cv = cum[n];
        outp[(size_t)n * KSEG + kstep] = valid ? (cv + rE[tid] - lse) : -1e9f;
        cum[n] = cv + rT[tid] - lse;
    }
#undef WOUT_ISSUE
}

// ---------------- host launch ----------------
static inline float* fsym(const void* sym) {
    void* p = nullptr; cudaGetSymbolAddress(&p, sym); return (float*)p;
}
static inline hf* hsym(const void* sym) {
    void* p = nullptr; cudaGetSymbolAddress(&p, sym); return (hf*)p;
}
static inline int* isym(const void* sym) {
    void* p = nullptr; cudaGetSymbolAddress(&p, sym); return (int*)p;
}

extern "C" void kernel_launch(void* const* d_in, const int* in_sizes, int n_in,
                              void* d_out, int out_size) {
    const int*   prev   = (const int*)d_in[0];
    const float* encO   = (const float*)d_in[1];
    const float* encH   = (const float*)d_in[2];
    const float* encC   = (const float*)d_in[3];
    const float* embed  = (const float*)d_in[4];
    const float* Wph    = (const float*)d_in[5];
    const float* bph    = (const float*)d_in[6];
    const float* Wpc    = (const float*)d_in[7];
    const float* bpc    = (const float*)d_in[8];
    const float* Wih0   = (const float*)d_in[9];
    const float* Whh0   = (const float*)d_in[10];
    const float* bih0   = (const float*)d_in[11];
    const float* bhh0   = (const float*)d_in[12];
    const float* Wih1   = (const float*)d_in[13];
    const float* Whh1   = (const float*)d_in[14];
    const float* bih1   = (const float*)d_in[15];
    const float* bhh1   = (const float*)d_in[16];
    const float* Wfc    = (const float*)d_in[17];
    const float* bfc    = (const float*)d_in[18];
    const float* Wout   = (const float*)d_in[19];
    const float* bout   = (const float*)d_in[20];
    float* outp = (float*)d_out;

    hf*    pX1   = hsym(d_X1);
    float* pc0   = fsym(d_c0);
    float* pc1   = fsym(d_c1);
    hf*    pfco  = hsym(d_fco);
    float* pgin  = fsym(d_gin);
    float* pgctx = fsym(d_gctx);
    hf*    pctxb = hsym(d_ctxb);
    float* pcum  = fsym(d_cum);
    float* pb0p  = fsym(d_b0p);
    float* pb1p  = fsym(d_b1p);
    int*   pgoff = isym(d_ginoff);
    int*   pcoff = isym(d_ctxoff);
    int*   ptgt  = isym(d_tgttok);
    hf*    pWhh0b  = hsym(d_Whh0b);
    hf*    pW1catb = hsym(d_W1catb);
    hf*    pWfcb   = hsym(d_Wfcb);
    hf*    pWoutb  = hsym(d_Woutb);
    hf*    pembb   = hsym(d_embb);
    hf*    pWih0b  = hsym(d_Wih0b);
    hf*    pWphb   = hsym(d_Wphb);
    hf*    pencOb  = hsym(d_encOb);

    // one-time stream/event setup (topology identical every capture)
    static bool s_init = false;
    static cudaStream_t sW;
    static cudaEvent_t evG1[KSEG], evFc[KSEG], evW[KSEG];
    if (!s_init) {
        cudaStreamCreateWithFlags(&sW, cudaStreamNonBlocking);
        for (int i = 0; i < KSEG; i++) {
            cudaEventCreateWithFlags(&evG1[i], cudaEventDisableTiming);
            cudaEventCreateWithFlags(&evFc[i], cudaEventDisableTiming);
            cudaEventCreateWithFlags(&evW[i], cudaEventDisableTiming);
        }
        s_init = true;
    }

    cudaFuncSetAttribute(gemm_hf<0, true,  false>, cudaFuncAttributeMaxDynamicSharedMemorySize, GSM_BYTES);
    cudaFuncSetAttribute(gemm_hf<1, true,  true >, cudaFuncAttributeMaxDynamicSharedMemorySize, GSM_BYTES);
    cudaFuncSetAttribute(gemm_hf<1, false, false>, cudaFuncAttributeMaxDynamicSharedMemorySize, GSM_BYTES);
    cudaFuncSetAttribute(gemm_hf<1, false, true >, cudaFuncAttributeMaxDynamicSharedMemorySize, GSM_BYTES);
    cudaFuncSetAttribute(gemm_hf<4, false, false>, cudaFuncAttributeMaxDynamicSharedMemorySize, GSM_BYTES);
    cudaFuncSetAttribute(gemm_hf<5, false, false>, cudaFuncAttributeMaxDynamicSharedMemorySize, GSM_BYTES);
    cudaFuncSetAttribute(wout_lse, cudaFuncAttributeMaxDynamicSharedMemorySize, WOUT_SMEM_BYTES);

    // ---- prologue: conversions / permutations ----
    wperm_kernel<<<(GHC * HC + 255) / 256, 256>>>(Whh0, pWhh0b, HC);
    w1catperm_kernel<<<(GHC * 1024 + 255) / 256, 256>>>(Wih1, Whh1);
    wperm_kernel<<<(GHC * (EC + HC) + 255) / 256, 256>>>(Wih0, pWih0b, EC + HC);
    biasperm_kernel<<<(GHC + 255) / 256, 256>>>(bih0, bhh0, bih1, bhh1);
    cvt_kernel<<<(EC * HC / 4 + 255) / 256, 256>>>(Wfc, pWfcb, EC * HC / 4);
    cvt_kernel<<<(VC * EC / 4 + 255) / 256, 256>>>(Wout, pWoutb, VC * EC / 4);
    cvt_kernel<<<((VC + 2) * EC / 4 + 255) / 256, 256>>>(embed, pembb, (VC + 2) * EC / 4);
    cvt_kernel<<<(HC * UC / 4 + 255) / 256, 256>>>(Wph, pWphb, HC * UC / 4);
    cvt_kernel<<<(T1C * BB * UC / 4 + 255) / 256, 256>>>(encO, pencOb, T1C * BB * UC / 4);

    tok_kernel<<<(GIN_ROWS_PAD + 255) / 256, 256>>>(prev);
    ctxoff_kernel<<<1, 256>>>();
    hcinit_kernel<<<(2 * BB * HC + 255) / 256, 256>>>(encH, encC, Wph, bph, Wpc, bpc);
    initX_kernel<<<(NN * HC) / 256, 256>>>();

    // ctx(fp16) = encO @ Wph^T + bph : M=256, N=512, K=1024 (gather A)
    gemm_hf<1, true, true><<<dim3(512 / 128, 256 / 128), 256, GSM_BYTES>>>(
        pencOb, 0, pWphb, UC, pctxb, HC, UC, pcoff, bph, nullptr, 0, nullptr, nullptr);
    // gctx = ctx @ Wih0p[:,E:]^T + b0p : M=256, N=2048(perm), K=512
    gemm_hf<1, false, false><<<dim3(GHC / 128, 256 / 128), 256, GSM_BYTES>>>(
        pctxb, HC, pWih0b + EC, EC + HC, pgctx, GHC, HC, nullptr, pb0p, nullptr, 0, nullptr, nullptr);
    // gin = emb @ Wih0p[:, :E]^T : M=2432, N=2048(perm), K=256 (gather A)
    gemm_hf<0, true, false><<<dim3(GHC / 128, GIN_ROWS_PAD / 128), 256, GSM_BYTES>>>(
        pembb, 0, pWih0b, EC + HC, pgin, GHC, EC, pgoff, nullptr, nullptr, 0, nullptr, nullptr);

    for (int k = 0; k < KSEG; k++) {
        hf* fcobuf = pfco + (size_t)(k & 1) * NN * EC;
        // layer 0 (s0): g0 = h0 @ Whh0p^T + gin + gctx, fused cell -> c0, h0.
        gemm_hf<4, false, false><<<dim3(GHC / 128, NN / 128), 256, GSM_BYTES>>>(
            pX1, 1024, pWhh0b, HC, nullptr, 0, HC, nullptr, pgin, pgctx, k, pc0, pX1);
        // layer 1 (s0): writes h1 — wait until fc(k-1) finished READING h1.
        if (k >= 1) cudaStreamWaitEvent(0, evFc[k - 1], 0);
        gemm_hf<5, false, false><<<dim3(GHC / 128, NN / 128), 256, GSM_BYTES>>>(
            pX1, 1024, pW1catb, 1024, nullptr, 0, 1024, nullptr, pb1p, nullptr, k, pc1, pX1 + 512);
        cudaEventRecord(evG1[k], 0);

        // fc(k) + wout(k) on side stream (fco buffer reuse ordered by sW FIFO)
        cudaStreamWaitEvent(sW, evG1[k], 0);
        gemm_hf<1, false, true><<<dim3(EC / 128, NN / 128), 256, GSM_BYTES, sW>>>(
            pX1 + 512, 1024, pWfcb, HC, fcobuf, EC, HC, nullptr, bfc, nullptr, 0, nullptr, nullptr);
        cudaEventRecord(evFc[k], sW);
        wout_lse<<<NN / 64, 256, WOUT_SMEM_BYTES, sW>>>(fcobuf, pWoutb, bout, ptgt, pcum, outp, k);
        cudaEventRecord(evW[k], sW);
    }
    // graph sink must depend on the last wout
    cudaStreamWaitEvent(0, evW[KSEG - 1], 0);
}

// round 16
// speedup vs baseline: 1.2035x; 1.0490x over previous
#include <cuda_runtime.h>
#include <cuda_fp16.h>
#include <mma.h>
#include <math.h>
#include <stdint.h>

using namespace nvcuda;

// ---------------- problem constants ----------------
#define BB 8
#define T1C 32
#define T2C 32
#define JC 33
#define KSEG 9
#define NN 8448
#define EC 256
#define HC 512
#define UC 1024
#define GHC 2048
#define VC 8000
#define START_ID 8001
#define GIN_ROWS 2376
#define GIN_ROWS_PAD 2432

typedef __half hf;
typedef __half2 hf2;

// ---------------- device scratch ----------------
__device__ hf    d_X1[NN * 1024];             // [h0 | h1] per row (fp16)
__device__ float d_c0[NN * HC];
__device__ float d_c1[NN * HC];
__device__ hf    d_fco[2 * NN * EC];          // double-buffered across steps
__device__ float d_gin[GIN_ROWS_PAD * GHC];
__device__ float d_gctx[256 * GHC];
__device__ hf    d_ctxb[256 * HC];
__device__ float d_hinit[2 * BB * HC];
__device__ float d_cinit[2 * BB * HC];
__device__ float d_cum[NN];
__device__ float d_b0p[GHC];
__device__ float d_b1p[GHC];
__device__ int   d_ginoff[GIN_ROWS_PAD];
__device__ int   d_ctxoff[256];
__device__ int   d_tgttok[GIN_ROWS];
__device__ hf d_Whh0b[GHC * HC];
__device__ hf d_W1catb[GHC * 1024];
__device__ hf d_Wfcb[EC * HC];
__device__ hf d_Woutb[VC * EC];
__device__ hf d_embb[(VC + 2) * EC];
__device__ hf d_Wih0b[GHC * (EC + HC)];
__device__ hf d_Wphb[HC * UC];
__device__ hf d_encOb[T1C * BB * UC];

__device__ __forceinline__ float tanha(float x) {
    float y; asm("tanh.approx.f32 %0, %1;" : "=f"(y) : "f"(x)); return y;
}
__device__ __forceinline__ float sigfast(float x) { return 0.5f * tanha(0.5f * x) + 0.5f; }

__device__ __forceinline__ void cpa16(void* dst, const void* src) {
    uint32_t d = (uint32_t)__cvta_generic_to_shared(dst);
    asm volatile("cp.async.cg.shared.global [%0], [%1], 16;\n" :: "r"(d), "l"(src));
}
__device__ __forceinline__ void cpa_commit() { asm volatile("cp.async.commit_group;\n"); }
template <int N> __device__ __forceinline__ void cpa_wait() {
    asm volatile("cp.async.wait_group %0;\n" :: "n"(N));
}

// ---------------- prologue kernels ----------------
__global__ void cvt_kernel(const float* __restrict__ src, hf* __restrict__ dst, int n4) {
    int i = blockIdx.x * blockDim.x + threadIdx.x;
    if (i >= n4) return;
    float4 v = ((const float4*)src)[i];
    hf2* d = (hf2*)dst + i * 2;
    d[0] = __floats2half2_rn(v.x, v.y);
    d[1] = __floats2half2_rn(v.z, v.w);
}

__global__ void wperm_kernel(const float* __restrict__ W, hf* __restrict__ dst, int ldw) {
    int idx = blockIdx.x * blockDim.x + threadIdx.x;
    if (idx >= GHC * ldw) return;
    int np = idx / ldw, c = idx - np * ldw;
    int h = np >> 2, gate = np & 3;
    dst[idx] = __float2half(W[(size_t)(gate * HC + h) * ldw + c]);
}

__global__ void w1catperm_kernel(const float* __restrict__ Wih1, const float* __restrict__ Whh1) {
    int idx = blockIdx.x * blockDim.x + threadIdx.x;
    if (idx >= GHC * 1024) return;
    int np = idx >> 10, c = idx & 1023;
    int o = (np & 3) * HC + (np >> 2);
    float v = (c < HC) ? Wih1[(size_t)o * HC + c] : Whh1[(size_t)o * HC + (c - HC)];
    d_W1catb[idx] = __float2half(v);
}

__global__ void biasperm_kernel(const float* __restrict__ bih0, const float* __restrict__ bhh0,
                                const float* __restrict__ bih1, const float* __restrict__ bhh1) {
    int idx = blockIdx.x * blockDim.x + threadIdx.x;
    if (idx >= GHC) return;
    int o = (idx & 3) * HC + (idx >> 2);
    d_b0p[idx] = bih0[o] + bhh0[o];
    d_b1p[idx] = bih1[o] + bhh1[o];
}

__global__ void tok_kernel(const int* __restrict__ prev) {
    int r = blockIdx.x * blockDim.x + threadIdx.x;
    if (r >= GIN_ROWS_PAD) return;
    if (r < GIN_ROWS) {
        int k = r / (BB * JC);
        int bj = r - k * (BB * JC);
        int b = bj / JC;
        int j = bj - b * JC;
        int pin = j + k - 1; if (pin > T2C - 1) pin = T2C - 1;
        int tin = (k == 0) ? START_ID : prev[b * T2C + pin];
        d_ginoff[r] = tin * EC;
        int pt = j + k; if (pt > T2C - 1) pt = T2C - 1;
        d_tgttok[r] = prev[b * T2C + pt];
    } else {
        d_ginoff[r] = 0;
    }
}

__global__ void ctxoff_kernel() {
    int r = threadIdx.x;
    if (r < 256) {
        int b = r / T1C, t1 = r - b * T1C;
        d_ctxoff[r] = t1 * (BB * UC) + b * UC;
    }
}

__global__ void hcinit_kernel(const float* __restrict__ ench, const float* __restrict__ encc,
                              const float* __restrict__ Wph, const float* __restrict__ bph,
                              const float* __restrict__ Wpc, const float* __restrict__ bpc) {
    int idx = blockIdx.x * blockDim.x + threadIdx.x;
    if (idx >= 2 * BB * HC) return;
    int l = idx / (BB * HC);
    int b = (idx / HC) % BB;
    int h = idx % HC;
    const float4* eh = (const float4*)(ench + l * BB * UC + b * UC);
    const float4* ec = (const float4*)(encc + l * BB * UC + b * UC);
    const float4* wh = (const float4*)(Wph + (size_t)h * UC);
    const float4* wc = (const float4*)(Wpc + (size_t)h * UC);
    float sh = 0.f, sc = 0.f;
    for (int u = 0; u < UC / 4; u++) {
        float4 a = eh[u], w = wh[u];
        sh += a.x * w.x + a.y * w.y + a.z * w.z + a.w * w.w;
        float4 a2 = ec[u], w2 = wc[u];
        sc += a2.x * w2.x + a2.y * w2.y + a2.z * w2.z + a2.w * w2.w;
    }
    d_hinit[idx] = sh + bph[h];
    d_cinit[idx] = sc + bpc[h];
}

__global__ void initX_kernel() {
    int idx = blockIdx.x * blockDim.x + threadIdx.x;
    if (idx >= NN * HC) return;
    int n = idx >> 9, h = idx & 511;
    int b = n / (T1C * JC);
    d_X1[(size_t)n * 1024 + h]       = __float2half(d_hinit[b * HC + h]);
    d_X1[(size_t)n * 1024 + 512 + h] = __float2half(d_hinit[BB * HC + b * HC + h]);
    d_c0[idx] = d_cinit[b * HC + h];
    d_c1[idx] = d_cinit[BB * HC + b * HC + h];
    if (h == 0) d_cum[n] = 0.f;
}

// ---------------- fp16 TN GEMM (f16 acc), 128x128 tile, BK=64, 2-stage ----------
// EPI: 0 none, 1 +e1[n], 4 CELL0 (+gin+gctx, cell), 5 CELL1 (+e1[n], cell)
#define SASTRIDE 72
#define STAGE_E (128 * SASTRIDE)
#define CSTRIDE 136
#define GSM_BYTES (2 * 2 * STAGE_E * 2)   // 73728; sC overlay 128*136*2=34816 fits
template <int EPI, bool GATHER, bool OBF>
__launch_bounds__(256)
__global__ void gemm_hf(const hf* __restrict__ A, int lda,
                        const hf* __restrict__ Bm, int ldb,
                        void* __restrict__ Cv, int ldc, int K,
                        const int* __restrict__ rowoff,
                        const float* __restrict__ e1, const float* __restrict__ e2,
                        int kstep, float* __restrict__ cptr, hf* __restrict__ hout) {
    extern __shared__ char smraw[];
    hf* sA = (hf*)smraw;                      // [2][128*72]
    hf* sB = sA + 2 * STAGE_E;                // [2][128*72]
    hf* sC = (hf*)smraw;                      // 128 x 136 overlay

    int tid = threadIdx.x;
    int m0 = blockIdx.y * 128, n0 = blockIdx.x * 128;
    int wid = tid >> 5;
    int wm = wid & 1, wn = wid >> 1;          // warp tile 64(m) x 32(n)

    wmma::fragment<wmma::accumulator, 16, 16, 16, hf> acc[4][2];
#pragma unroll
    for (int mi = 0; mi < 4; mi++)
#pragma unroll
        for (int ni = 0; ni < 2; ni++) wmma::fill_fragment(acc[mi][ni], __float2half(0.0f));

    int nk = K >> 6;   // BK=64; all call sites K % 64 == 0, nk >= 4

#define GEMM_ISSUE(S)                                                                    \
    {                                                                                    \
        int buf_ = (S) & 1;                                                              \
        int k0_ = (S) << 6;                                                              \
        _Pragma("unroll")                                                                \
        for (int i_ = 0; i_ < 4; i_++) {                                                 \
            int idx_ = tid + i_ * 256;                                                   \
            int r_ = idx_ >> 3, c_ = idx_ & 7;                                           \
            const hf* src_ = GATHER ? (A + rowoff[m0 + r_] + k0_ + c_ * 8)               \
                                    : (A + (size_t)(m0 + r_) * lda + k0_ + c_ * 8);      \
            cpa16(sA + buf_ * STAGE_E + r_ * SASTRIDE + c_ * 8, src_);                   \
        }                                                                                \
        _Pragma("unroll")                                                                \
        for (int i_ = 0; i_ < 4; i_++) {                                                 \
            int idx_ = tid + i_ * 256;                                                   \
            int r_ = idx_ >> 3, c_ = idx_ & 7;                                           \
            cpa16(sB + buf_ * STAGE_E + r_ * SASTRIDE + c_ * 8,                          \
                  Bm + (size_t)(n0 + r_) * ldb + k0_ + c_ * 8);                          \
        }                                                                                \
        cpa_commit();                                                                    \
    }

    GEMM_ISSUE(0);
    for (int s = 0; s < nk; s++) {
        cpa_wait<0>();
        __syncthreads();
        if (s + 1 < nk) GEMM_ISSUE(s + 1);
        int buf = s & 1;
        const hf* a_base = sA + buf * STAGE_E;
        const hf* b_base = sB + buf * STAGE_E;
#pragma unroll
        for (int kk = 0; kk < 4; kk++) {
            wmma::fragment<wmma::matrix_a, 16, 16, 16, hf, wmma::row_major> af[4];
            wmma::fragment<wmma::matrix_b, 16, 16, 16, hf, wmma::col_major> bfr[2];
#pragma unroll
            for (int mi = 0; mi < 4; mi++)
                wmma::load_matrix_sync(af[mi], a_base + (wm * 64 + mi * 16) * SASTRIDE + kk * 16, SASTRIDE);
#pragma unroll
            for (int ni = 0; ni < 2; ni++)
                wmma::load_matrix_sync(bfr[ni], b_base + (wn * 32 + ni * 16) * SASTRIDE + kk * 16, SASTRIDE);
#pragma unroll
            for (int mi = 0; mi < 4; mi++)
#pragma unroll
                for (int ni = 0; ni < 2; ni++)
                    wmma::mma_sync(acc[mi][ni], af[mi], bfr[ni], acc[mi][ni]);
        }
    }
    __syncthreads();
#pragma unroll
    for (int mi = 0; mi < 4; mi++)
#pragma unroll
        for (int ni = 0; ni < 2; ni++)
            wmma::store_matrix_sync(sC + (wm * 64 + mi * 16) * CSTRIDE + wn * 32 + ni * 16,
                                    acc[mi][ni], CSTRIDE, wmma::mem_row_major);
    __syncthreads();

#pragma unroll
    for (int i = 0; i < 16; i++) {
        int idx = tid + i * 256;
        int r = idx >> 5, c4 = idx & 31;
        uint2 raw = *(uint2*)(sC + r * CSTRIDE + c4 * 4);
        hf2 p0 = *(hf2*)&raw.x;
        hf2 p1 = *(hf2*)&raw.y;
        float4 v = make_float4(__low2float(p0), __high2float(p0),
                               __low2float(p1), __high2float(p1));
        int m = m0 + r;
        int nb = n0 + c4 * 4;
        if (EPI == 1 || EPI == 5) {
            float4 bb = *(const float4*)(e1 + nb);
            v.x += bb.x; v.y += bb.y; v.z += bb.z; v.w += bb.w;
        }
        if (EPI == 4) {
            int b = m / (T1C * JC);
            int rem = m - b * (T1C * JC);
            int t1 = rem / JC;
            int j = rem - t1 * JC;
            const float* gi = e1 + (size_t)((kstep * BB + b) * JC + j) * GHC + nb;
            const float* gc = e2 + (size_t)(b * T1C + t1) * GHC + nb;
            float4 a1 = *(const float4*)gi;
            float4 a2 = *(const float4*)gc;
            v.x += a1.x + a2.x; v.y += a1.y + a2.y; v.z += a1.z + a2.z; v.w += a1.w + a2.w;
        }
        if (EPI == 4 || EPI == 5) {
            int h = nb >> 2;
            size_t cix = (size_t)m * HC + h;
            float cold = cptr[cix];
            float cn = sigfast(v.y) * cold + sigfast(v.x) * tanha(v.z);
            cptr[cix] = cn;
            hout[(size_t)m * 1024 + h] = __float2half(sigfast(v.w) * tanha(cn));
        } else if (OBF) {
            hf2* p = (hf2*)((hf*)Cv + (size_t)m * ldc + nb);
            p[0] = __floats2half2_rn(v.x, v.y);
            p[1] = __floats2half2_rn(v.z, v.w);
        } else {
            *(float4*)((float*)Cv + (size_t)m * ldc + nb) = v;
        }
    }
#undef GEMM_ISSUE
}

// ---------------- fused Wout GEMM + online LSE; A fragments cached (R15 proven) ------
#define WA_STRIDE 264
#define WB_STRIDE 264
#define WC_STRIDE 72
#define WOUT_SMEM_BYTES (64 * WA_STRIDE * 2 + 2 * 64 * WB_STRIDE * 2 + 64 * WC_STRIDE * 2 + 64 * 5 * 4)
__launch_bounds__(256)
__global__ void wout_lse(const hf* __restrict__ fco, const hf* __restrict__ Wout,
                         const float* __restrict__ bout, const int* __restrict__ tgttok,
                         float* __restrict__ cum, float* __restrict__ outp, int kstep) {
    extern __shared__ char smraw[];
    hf* A_s = (hf*)smraw;                            // 64 x 264
    hf* B_s = A_s + 64 * WA_STRIDE;                  // 2 x 64 x 264
    hf* C_s = B_s + 2 * 64 * WB_STRIDE;              // 64 x 72
    float* rM = (float*)(C_s + 64 * WC_STRIDE);
    float* rS = rM + 64;
    float* rE = rS + 64;
    float* rT = rE + 64;
    int* rTgt = (int*)(rT + 64);

    int tid = threadIdx.x;
    int m0 = blockIdx.x * 64;

#pragma unroll
    for (int i = 0; i < 8; i++) {        // A: 64 x 256 halves
        int idx = tid + i * 256;
        int r = idx >> 5, c = idx & 31;
        *(uint4*)(A_s + r * WA_STRIDE + c * 8) = *(const uint4*)(fco + (size_t)(m0 + r) * EC + c * 8);
    }
    if (tid < 64) {
        int n = m0 + tid;
        int b = n / (T1C * JC);
        int rem = n - b * (T1C * JC);
        int j = rem % JC;
        rTgt[tid] = tgttok[(kstep * BB + b) * JC + j];
        rM[tid] = -1e30f; rS[tid] = 0.f; rE[tid] = 0.f; rT[tid] = 0.f;
    }

    int wid = tid >> 5;
    int wm = wid >> 1, wn = wid & 1;     // warp tile 16(m) x 32(n)

#define WOUT_ISSUE(S)                                                                  \
    {                                                                                  \
        int buf_ = (S) & 1;                                                            \
        _Pragma("unroll")                                                              \
        for (int i_ = 0; i_ < 8; i_++) {                                               \
            int idx_ = tid + i_ * 256;                                                 \
            int r_ = idx_ >> 5, c_ = idx_ & 31;                                        \
            cpa16(B_s + buf_ * (64 * WB_STRIDE) + r_ * WB_STRIDE + c_ * 8,             \
                  Wout + (size_t)((S) * 64 + r_) * EC + c_ * 8);                       \
        }                                                                              \
        cpa_commit();                                                                  \
    }

    WOUT_ISSUE(0);
    __syncthreads();   // A_s + rTgt visible

    // cache the warp's 16 A fragments (one per kk) in registers
    wmma::fragment<wmma::matrix_a, 16, 16, 16, hf, wmma::row_major> afc[16];
#pragma unroll
    for (int kk = 0; kk < 16; kk++)
        wmma::load_matrix_sync(afc[kk], A_s + (wm * 16) * WA_STRIDE + kk * 16, WA_STRIDE);

    const int NCC = VC / 64;
    for (int nc = 0; nc < NCC; nc++) {
        cpa_wait<0>();
        __syncthreads();
        if (nc + 1 < NCC) WOUT_ISSUE(nc + 1);
        int buf = nc & 1;
        const hf* b_base = B_s + buf * (64 * WB_STRIDE);

        wmma::fragment<wmma::accumulator, 16, 16, 16, hf> acc[2];
        wmma::fill_fragment(acc[0], __float2half(0.0f));
        wmma::fill_fragment(acc[1], __float2half(0.0f));
#pragma unroll
        for (int kk = 0; kk < 16; kk++) {
            wmma::fragment<wmma::matrix_b, 16, 16, 16, hf, wmma::col_major> bfr;
            wmma::load_matrix_sync(bfr, b_base + (wn * 32) * WB_STRIDE + kk * 16, WB_STRIDE);
            wmma::mma_sync(acc[0], afc[kk], bfr, acc[0]);
            wmma::load_matrix_sync(bfr, b_base + (wn * 32 + 16) * WB_STRIDE + kk * 16, WB_STRIDE);
            wmma::mma_sync(acc[1], afc[kk], bfr, acc[1]);
        }
        wmma::store_matrix_sync(C_s + (wm * 16) * WC_STRIDE + wn * 32, acc[0], WC_STRIDE, wmma::mem_row_major);
        wmma::store_matrix_sync(C_s + (wm * 16) * WC_STRIDE + wn * 32 + 16, acc[1], WC_STRIDE, wmma::mem_row_major);
        __syncthreads();

        {   // online LSE over this 64-col chunk: 4 lanes per row, 16 cols each
            int n0v = nc * 64;
            int r = tid >> 2, q = tid & 3;
            int tgt = rTgt[r];
            float lv[16];
            float lm = -1e30f;
#pragma unroll
            for (int c = 0; c < 16; c++) {
                int col = q * 16 + c;
                int gcol = n0v + col;
                float l = __half2float(C_s[r * WC_STRIDE + col]) + bout[gcol];
                lv[c] = l;
                lm = fmaxf(lm, l);
                if (gcol == 2) rE[r] = l;
                if (gcol == tgt) rT[r] = l;
            }
            float ls = 0.f;
#pragma unroll
            for (int c = 0; c < 16; c++) ls += __expf(lv[c] - lm);
#pragma unroll
            for (int off = 1; off < 4; off <<= 1) {
                float om = __shfl_xor_sync(0xffffffffu, lm, off);
                float os = __shfl_xor_sync(0xffffffffu, ls, off);
                float nm = fmaxf(lm, om);
                ls = ls * __expf(lm - nm) + os * __expf(om - nm);
                lm = nm;
            }
            if (q == 0) {
                float M = rM[r], S = rS[r];
                float nm = fmaxf(M, lm);
                rS[r] = S * __expf(M - nm) + ls * __expf(lm - nm);
                rM[r] = nm;
            }
        }
        __syncthreads();
    }

    if (tid < 64) {
        int n = m0 + tid;
        float lse = rM[tid] + logf(rS[tid]);
        int j = n % JC;
        bool valid = (j + kstep) <= T2C;
        float cv = cum[n];
        outp[(size_t)n * KSEG + kstep] = valid ? (cv + rE[tid] - lse) : -1e9f;
        cum[n] = cv + rT[tid] - lse;
    }
#undef WOUT_ISSUE
}

// ---------------- host launch ----------------
static inline float* fsym(const void* sym) {
    void* p = nullptr; cudaGetSymbolAddress(&p, sym); return (float*)p;
}
static inline hf* hsym(const void* sym) {
    void* p = nullptr; cudaGetSymbolAddress(&p, sym); return (hf*)p;
}
static inline int* isym(const void* sym) {
    void* p = nullptr; cudaGetSymbolAddress(&p, sym); return (int*)p;
}

extern "C" void kernel_launch(void* const* d_in, const int* in_sizes, int n_in,
                              void* d_out, int out_size) {
    const int*   prev   = (const int*)d_in[0];
    const float* encO   = (const float*)d_in[1];
    const float* encH   = (const float*)d_in[2];
    const float* encC   = (const float*)d_in[3];
    const float* embed  = (const float*)d_in[4];
    const float* Wph    = (const float*)d_in[5];
    const float* bph    = (const float*)d_in[6];
    const float* Wpc    = (const float*)d_in[7];
    const float* bpc    = (const float*)d_in[8];
    const float* Wih0   = (const float*)d_in[9];
    const float* Whh0   = (const float*)d_in[10];
    const float* bih0   = (const float*)d_in[11];
    const float* bhh0   = (const float*)d_in[12];
    const float* Wih1   = (const float*)d_in[13];
    const float* Whh1   = (const float*)d_in[14];
    const float* bih1   = (const float*)d_in[15];
    const float* bhh1   = (const float*)d_in[16];
    const float* Wfc    = (const float*)d_in[17];
    const float* bfc    = (const float*)d_in[18];
    const float* Wout   = (const float*)d_in[19];
    const float* bout   = (const float*)d_in[20];
    float* outp = (float*)d_out;

    hf*    pX1   = hsym(d_X1);
    float* pc0   = fsym(d_c0);
    float* pc1   = fsym(d_c1);
    hf*    pfco  = hsym(d_fco);
    float* pgin  = fsym(d_gin);
    float* pgctx = fsym(d_gctx);
    hf*    pctxb = hsym(d_ctxb);
    float* pcum  = fsym(d_cum);
    float* pb0p  = fsym(d_b0p);
    float* pb1p  = fsym(d_b1p);
    int*   pgoff = isym(d_ginoff);
    int*   pcoff = isym(d_ctxoff);
    int*   ptgt  = isym(d_tgttok);
    hf*    pWhh0b  = hsym(d_Whh0b);
    hf*    pW1catb = hsym(d_W1catb);
    hf*    pWfcb   = hsym(d_Wfcb);
    hf*    pWoutb  = hsym(d_Woutb);
    hf*    pembb   = hsym(d_embb);
    hf*    pWih0b  = hsym(d_Wih0b);
    hf*    pWphb   = hsym(d_Wphb);
    hf*    pencOb  = hsym(d_encOb);

    // one-time stream/event setup (topology identical every capture)
    static bool s_init = false;
    static cudaStream_t sW;
    static cudaEvent_t evG1[KSEG], evFc[KSEG], evW[KSEG];
    if (!s_init) {
        cudaStreamCreateWithFlags(&sW, cudaStreamNonBlocking);
        for (int i = 0; i < KSEG; i++) {
            cudaEventCreateWithFlags(&evG1[i], cudaEventDisableTiming);
            cudaEventCreateWithFlags(&evFc[i], cudaEventDisableTiming);
            cudaEventCreateWithFlags(&evW[i], cudaEventDisableTiming);
        }
        s_init = true;
    }

    cudaFuncSetAttribute(gemm_hf<0, true,  false>, cudaFuncAttributeMaxDynamicSharedMemorySize, GSM_BYTES);
    cudaFuncSetAttribute(gemm_hf<1, true,  true >, cudaFuncAttributeMaxDynamicSharedMemorySize, GSM_BYTES);
    cudaFuncSetAttribute(gemm_hf<1, false, false>, cudaFuncAttributeMaxDynamicSharedMemorySize, GSM_BYTES);
    cudaFuncSetAttribute(gemm_hf<1, false, true >, cudaFuncAttributeMaxDynamicSharedMemorySize, GSM_BYTES);
    cudaFuncSetAttribute(gemm_hf<4, false, false>, cudaFuncAttributeMaxDynamicSharedMemorySize, GSM_BYTES);
    cudaFuncSetAttribute(gemm_hf<5, false, false>, cudaFuncAttributeMaxDynamicSharedMemorySize, GSM_BYTES);
    cudaFuncSetAttribute(wout_lse, cudaFuncAttributeMaxDynamicSharedMemorySize, WOUT_SMEM_BYTES);

    // ---- prologue: conversions / permutations ----
    wperm_kernel<<<(GHC * HC + 255) / 256, 256>>>(Whh0, pWhh0b, HC);
    w1catperm_kernel<<<(GHC * 1024 + 255) / 256, 256>>>(Wih1, Whh1);
    wperm_kernel<<<(GHC * (EC + HC) + 255) / 256, 256>>>(Wih0, pWih0b, EC + HC);
    biasperm_kernel<<<(GHC + 255) / 256, 256>>>(bih0, bhh0, bih1, bhh1);
    cvt_kernel<<<(EC * HC / 4 + 255) / 256, 256>>>(Wfc, pWfcb, EC * HC / 4);
    cvt_kernel<<<(VC * EC / 4 + 255) / 256, 256>>>(Wout, pWoutb, VC * EC / 4);
    cvt_kernel<<<((VC + 2) * EC / 4 + 255) / 256, 256>>>(embed, pembb, (VC + 2) * EC / 4);
    cvt_kernel<<<(HC * UC / 4 + 255) / 256, 256>>>(Wph, pWphb, HC * UC / 4);
    cvt_kernel<<<(T1C * BB * UC / 4 + 255) / 256, 256>>>(encO, pencOb, T1C * BB * UC / 4);

    tok_kernel<<<(GIN_ROWS_PAD + 255) / 256, 256>>>(prev);
    ctxoff_kernel<<<1, 256>>>();
    hcinit_kernel<<<(2 * BB * HC + 255) / 256, 256>>>(encH, encC, Wph, bph, Wpc, bpc);
    initX_kernel<<<(NN * HC) / 256, 256>>>();

    // ctx(fp16) = encO @ Wph^T + bph : M=256, N=512, K=1024 (gather A)
    gemm_hf<1, true, true><<<dim3(512 / 128, 256 / 128), 256, GSM_BYTES>>>(
        pencOb, 0, pWphb, UC, pctxb, HC, UC, pcoff, bph, nullptr, 0, nullptr, nullptr);
    // gctx = ctx @ Wih0p[:,E:]^T + b0p : M=256, N=2048(perm), K=512
    gemm_hf<1, false, false><<<dim3(GHC / 128, 256 / 128), 256, GSM_BYTES>>>(
        pctxb, HC, pWih0b + EC, EC + HC, pgctx, GHC, HC, nullptr, pb0p, nullptr, 0, nullptr, nullptr);
    // gin = emb @ Wih0p[:, :E]^T : M=2432, N=2048(perm), K=256 (gather A)
    gemm_hf<0, true, false><<<dim3(GHC / 128, GIN_ROWS_PAD / 128), 256, GSM_BYTES>>>(
        pembb, 0, pWih0b, EC + HC, pgin, GHC, EC, pgoff, nullptr, nullptr, 0, nullptr, nullptr);

    for (int k = 0; k < KSEG; k++) {
        hf* fcobuf = pfco + (size_t)(k & 1) * NN * EC;
        // layer 0 (s0): g0 = h0 @ Whh0p^T + gin + gctx, fused cell -> c0, h0.
        gemm_hf<4, false, false><<<dim3(GHC / 128, NN / 128), 256, GSM_BYTES>>>(
            pX1, 1024, pWhh0b, HC, nullptr, 0, HC, nullptr, pgin, pgctx, k, pc0, pX1);
        // layer 1 (s0): writes h1 — wait until fc(k-1) finished READING h1.
        if (k >= 1) cudaStreamWaitEvent(0, evFc[k - 1], 0);
        gemm_hf<5, false, false><<<dim3(GHC / 128, NN / 128), 256, GSM_BYTES>>>(
            pX1, 1024, pW1catb, 1024, nullptr, 0, 1024, nullptr, pb1p, nullptr, k, pc1, pX1 + 512);
        cudaEventRecord(evG1[k], 0);

        // fc(k) + wout(k) on side stream (fco buffer reuse ordered by sW FIFO)
        cudaStreamWaitEvent(sW, evG1[k], 0);
        gemm_hf<1, false, true><<<dim3(EC / 128, NN / 128), 256, GSM_BYTES, sW>>>(
            pX1 + 512, 1024, pWfcb, HC, fcobuf, EC, HC, nullptr, bfc, nullptr, 0, nullptr, nullptr);
        cudaEventRecord(evFc[k], sW);
        wout_lse<<<NN / 64, 256, WOUT_SMEM_BYTES, sW>>>(fcobuf, pWoutb, bout, ptgt, pcum, outp, k);
        cudaEventRecord(evW[k], sW);
    }
    // graph sink must depend on the last wout
    cudaStreamWaitEvent(0, evW[KSEG - 1], 0);
}